// round 7
// baseline (speedup 1.0000x reference)
#include <cuda_runtime.h>
#include <cstdint>

// MXFP8 E4M3 quantize->dequantize, 32-element blocks along last axis.
// R6: persistent grid-stride kernel. 304 CTAs (2 resident per SM, exactly one
// wave) each loop ~27 iterations; eliminates the CTA launch ramp/drain churn
// of 8192 short-lived CTAs that held achieved occupancy at 78.6%.
// Per iteration: 4 front-batched fully-coalesced LDG.128 from the four fixed
// quarters of the array (proven R2/R5 MLP shape), process + store each.
//
// 8 lanes per MX block, amax via 3x shfl.xor (xor 1,2,4); quarter stride is
// a multiple of 8 float4s so shfl groups stay block-aligned in every stream.
//
// All scales are exact powers of two built by bit manipulation, so every
// multiply matches the reference's fp32 divide bit-for-bit.

static constexpr int EMAX = 8;           // e4m3
static constexpr float MAX_NORM = 448.0f;

__device__ __forceinline__ float quant_e4m3(float x, float iscale, float scale) {
    float a = x * iscale;                          // exact (iscale = 2^k)
    uint32_t au = __float_as_uint(a);
    uint32_t ab = au & 0x7fffffffu;                // |a|
    int pe = (int)(ab >> 23) - 127;                // floor(log2|a|), exact for normals
    pe = max(pe, -6);                              // MIN_EXP (denorm region clamp)
    // lshift = 2^(3-pe), inv_lshift = 2^(pe-3); pe in [-6, 8] -> both normal
    float lsh  = __uint_as_float((uint32_t)(130 - pe) << 23);
    float ilsh = __uint_as_float((uint32_t)(124 + pe) << 23);
    // round-half-away-from-zero on magnitude: product is exact, +0.5 rounds once
    float r = floorf(__uint_as_float(ab) * lsh + 0.5f);
    float m = fminf(r * ilsh, MAX_NORM);           // saturate to e4m3 max normal
    float res = m * scale;
    return __uint_as_float(__float_as_uint(res) | (au & 0x80000000u));
}

__device__ __forceinline__ float4 process4(float4 v) {
    float ax = fmaxf(fmaxf(fabsf(v.x), fabsf(v.y)), fmaxf(fabsf(v.z), fabsf(v.w)));
    ax = fmaxf(ax, __shfl_xor_sync(0xffffffffu, ax, 1));
    ax = fmaxf(ax, __shfl_xor_sync(0xffffffffu, ax, 2));
    ax = fmaxf(ax, __shfl_xor_sync(0xffffffffu, ax, 4));

    int e = (int)(__float_as_uint(ax) >> 23);      // ax >= 0, no sign bit
    int se = e - 127 - EMAX;
    se = max(se, -127);
    float scale  = __uint_as_float((uint32_t)(se + 127) << 23);
    float iscale = __uint_as_float((uint32_t)(127 - se) << 23);

    v.x = quant_e4m3(v.x, iscale, scale);
    v.y = quant_e4m3(v.y, iscale, scale);
    v.z = quant_e4m3(v.z, iscale, scale);
    v.w = quant_e4m3(v.w, iscale, scale);
    return v;
}

__global__ void __launch_bounds__(512) mxq_kernel(const float4* __restrict__ in,
                                                  float4* __restrict__ out,
                                                  int quarter,   // n4 / 4
                                                  int step) {    // gridDim*blockDim
    int gid = blockIdx.x * blockDim.x + threadIdx.x;

    for (int idx = gid; idx < quarter; idx += step) {
        // Front-batched fully-coalesced independent loads (MLP_p1 = 4),
        // one from each fixed quarter of the array.
        float4 v0 = __ldcs(&in[idx]);
        float4 v1 = __ldcs(&in[idx + quarter]);
        float4 v2 = __ldcs(&in[idx + 2 * quarter]);
        float4 v3 = __ldcs(&in[idx + 3 * quarter]);

        v0 = process4(v0);
        __stcs(&out[idx], v0);
        v1 = process4(v1);
        __stcs(&out[idx + quarter], v1);
        v2 = process4(v2);
        __stcs(&out[idx + 2 * quarter], v2);
        v3 = process4(v3);
        __stcs(&out[idx + 3 * quarter], v3);
    }
}

extern "C" void kernel_launch(void* const* d_in, const int* in_sizes, int n_in,
                              void* d_out, int out_size) {
    const float4* in = (const float4*)d_in[0];
    float4* out = (float4*)d_out;
    int n4 = out_size / 4;                         // 16,777,216 float4s
    int quarter = n4 / 4;                          // 4,194,304
    int threads = 512;
    int blocks = 304;                              // 2 resident CTAs x 152 SMs, one wave
    int step = blocks * threads;                   // 155,648
    mxq_kernel<<<blocks, threads>>>(in, out, quarter, step);
}

// round 8
// speedup vs baseline: 1.1448x; 1.1448x over previous
#include <cuda_runtime.h>
#include <cstdint>

// MXFP8 E4M3 quantize->dequantize, 32-element blocks along last axis.
// R7: 256-bit global loads/stores (sm_103a LDG.E.256 / STG.E.256 via
// ld/st.global.v8.f32). Each thread owns 8 CONTIGUOUS floats per stream,
// 2 independent streams: same 16 lines-in-flight per warp as the proven R2
// shape, but half the memory instructions and an MX block spans only 4
// lanes -> 2 shfl.xor per 8 elements (was 3 per 4). Fully coalesced:
// one warp-level 256-bit op covers 1KiB contiguous.
//
// All scales are exact powers of two built by bit manipulation, so every
// multiply matches the reference's fp32 divide bit-for-bit.

static constexpr int EMAX = 8;           // e4m3
static constexpr float MAX_NORM = 448.0f;

__device__ __forceinline__ void ldg256(const float* p, float* v) {
    asm volatile(
        "ld.global.v8.f32 {%0,%1,%2,%3,%4,%5,%6,%7}, [%8];"
        : "=f"(v[0]), "=f"(v[1]), "=f"(v[2]), "=f"(v[3]),
          "=f"(v[4]), "=f"(v[5]), "=f"(v[6]), "=f"(v[7])
        : "l"(p));
}

__device__ __forceinline__ void stg256(float* p, const float* v) {
    asm volatile(
        "st.global.v8.f32 [%0], {%1,%2,%3,%4,%5,%6,%7,%8};"
        :: "l"(p),
           "f"(v[0]), "f"(v[1]), "f"(v[2]), "f"(v[3]),
           "f"(v[4]), "f"(v[5]), "f"(v[6]), "f"(v[7])
        : "memory");
}

__device__ __forceinline__ float quant_e4m3(float x, float iscale, float scale) {
    float a = x * iscale;                          // exact (iscale = 2^k)
    uint32_t au = __float_as_uint(a);
    uint32_t ab = au & 0x7fffffffu;                // |a|
    int pe = (int)(ab >> 23) - 127;                // floor(log2|a|), exact for normals
    pe = max(pe, -6);                              // MIN_EXP (denorm region clamp)
    // lshift = 2^(3-pe), inv_lshift = 2^(pe-3); pe in [-6, 8] -> both normal
    float lsh  = __uint_as_float((uint32_t)(130 - pe) << 23);
    float ilsh = __uint_as_float((uint32_t)(124 + pe) << 23);
    // round-half-away-from-zero on magnitude: product is exact, +0.5 rounds once
    float r = floorf(__uint_as_float(ab) * lsh + 0.5f);
    float m = fminf(r * ilsh, MAX_NORM);           // saturate to e4m3 max normal
    float res = m * scale;
    return __uint_as_float(__float_as_uint(res) | (au & 0x80000000u));
}

// Process 8 contiguous floats; MX block = this thread's 8 plus 3 neighbor
// lanes' (4-lane groups, xor 1 / xor 2 reduce — lane group == block group).
__device__ __forceinline__ void process8(float* v) {
    float m01 = fmaxf(fabsf(v[0]), fabsf(v[1]));
    float m23 = fmaxf(fabsf(v[2]), fabsf(v[3]));
    float m45 = fmaxf(fabsf(v[4]), fabsf(v[5]));
    float m67 = fmaxf(fabsf(v[6]), fabsf(v[7]));
    float m = fmaxf(fmaxf(m01, m23), fmaxf(m45, m67));
    m = fmaxf(m, __shfl_xor_sync(0xffffffffu, m, 1));
    m = fmaxf(m, __shfl_xor_sync(0xffffffffu, m, 2));

    int e = (int)(__float_as_uint(m) >> 23);       // m >= 0, no sign bit
    int se = e - 127 - EMAX;
    se = max(se, -127);
    float scale  = __uint_as_float((uint32_t)(se + 127) << 23);
    float iscale = __uint_as_float((uint32_t)(127 - se) << 23);

#pragma unroll
    for (int i = 0; i < 8; i++)
        v[i] = quant_e4m3(v[i], iscale, scale);
}

__global__ void __launch_bounds__(512) mxq_kernel(const float* __restrict__ in,
                                                  float* __restrict__ out,
                                                  int strideF) {   // floats between streams
    int gid = blockIdx.x * blockDim.x + threadIdx.x;
    int base = gid * 8;                            // 8 contiguous floats

    // Front-batched independent 256-bit loads (16 lines in flight per warp)
    float a[8], b[8];
    ldg256(in + base, a);
    ldg256(in + base + strideF, b);

    process8(a);
    stg256(out + base, a);
    process8(b);
    stg256(out + base + strideF, b);
}

extern "C" void kernel_launch(void* const* d_in, const int* in_sizes, int n_in,
                              void* d_out, int out_size) {
    const float* in = (const float*)d_in[0];
    float* out = (float*)d_out;
    int n = out_size;                              // 67,108,864 floats
    int threads = 512;
    int total_threads = n / 16;                    // 16 floats per thread
    int blocks = total_threads / threads;          // 8192
    int strideF = total_threads * 8;               // float gap between the 2 streams
    mxq_kernel<<<blocks, threads>>>(in, out, strideF);
}